// round 4
// baseline (speedup 1.0000x reference)
#include <cuda_runtime.h>
#include <mma.h>
#include <cstdint>

using namespace nvcuda;

#define Bn  4
#define Ln  1024
#define Dn  768
#define Hn  6
#define DHn 128
#define BHn (Bn*Hn)
#define EPSf 1e-5f

#define KC   32                 /* k-chunk */
#define CHLD 36                 /* chunk leading dim (32+4) */
#define STAGE_F (128*CHLD*2)    /* floats per stage (A+B) = 9216 */
#define CLD  132                /* epilogue staging leading dim */

#define OFF_CO 0
#define OFF_W  (BHn*Ln*Ln)          /* 25165824 */
#define OFF_V  (OFF_W + Bn*Ln)      /* 25169920 */

// ---------------- scratch ----------------
__device__ float  g_q2[BHn*Ln];
__device__ float  g_k2[BHn*Ln];
__device__ double g_sum1[Hn];
__device__ double g_sumsq1[Hn];
__device__ float  g_scale1[Hn];
__device__ float  g_shift1[Hn];
__device__ float  g_w[BHn*Ln];
__device__ float  g_scale2[Hn];
__device__ float  g_shift2[Hn];
__device__ float  g_p[Bn*Ln];
__device__ unsigned char g_valid[Bn*Ln];

__device__ __forceinline__ void cp_async16(uint32_t smem_addr, const void* gptr) {
    asm volatile("cp.async.cg.shared.global [%0], [%1], 16;" :: "r"(smem_addr), "l"(gptr));
}
#define CP_COMMIT() asm volatile("cp.async.commit_group;")
#define CP_WAIT(n)  asm volatile("cp.async.wait_group %0;" :: "n"(n))

// ---------------- zero accumulators ----------------
__global__ void zero_kernel() {
    int idx = blockIdx.x*blockDim.x + threadIdx.x;
    if (idx < BHn*Ln) g_w[idx] = 0.f;
    if (idx < Hn) { g_sum1[idx] = 0.0; g_sumsq1[idx] = 0.0; }
}

// ---------------- mask: derive valid[] from bx_packed with dtype sniff ----------------
__global__ void mask_kernel(const unsigned int* w) {
    __shared__ int s_float, s_byte;
    if (threadIdx.x == 0) { s_float = 0; s_byte = 0; }
    __syncthreads();
    for (int i = threadIdx.x; i < (Bn*Ln)/4; i += blockDim.x) {
        unsigned v = w[i];
        if (v == 0x3f800000u) atomicOr(&s_float, 1);
        else if (v > 1u)      atomicOr(&s_byte, 1);
    }
    __syncthreads();
    int byte_mode = (!s_float) && s_byte;
    const unsigned char* bytes = (const unsigned char*)w;
    for (int i = threadIdx.x; i < Bn*Ln; i += blockDim.x) {
        bool padded = byte_mode ? (bytes[i] != 0) : (w[i] != 0u);
        g_valid[i] = padded ? 0 : 1;
    }
}

// ---------------- Vh output: transpose copy ----------------
__global__ void vout_kernel(const float* __restrict__ V, float* __restrict__ out) {
    int idx = blockIdx.x*blockDim.x + threadIdx.x;
    if (idx >= BHn*Ln*DHn/4) return;
    int d4 = idx & 31;
    int l  = (idx >> 5) & (Ln-1);
    int h  = (idx >> 15) % Hn;
    int b  = idx / (32*Ln*Hn);
    float4 v = *(const float4*)(V + ((size_t)(b*Ln + l))*Dn + h*DHn + d4*4);
    ((float4*)(out + OFF_V))[idx] = v;
}

// ---------------- squared norms per head-row (fp32 exact) ----------------
__global__ void sq_kernel(const float* __restrict__ Q, const float* __restrict__ K) {
    int warp = (blockIdx.x*blockDim.x + threadIdx.x) >> 5;
    int lane = threadIdx.x & 31;
    if (warp >= 2*BHn*Ln) return;
    int t  = warp / (BHn*Ln);
    int rr = warp % (BHn*Ln);
    int bh = rr / Ln, i = rr % Ln;
    int b = bh / Hn, h = bh % Hn;
    const float* src = (t ? K : Q) + ((size_t)(b*Ln + i))*Dn + h*DHn;
    float4 x = ((const float4*)src)[lane];
    float s = x.x*x.x + x.y*x.y + x.z*x.z + x.w*x.w;
    #pragma unroll
    for (int o = 16; o; o >>= 1) s += __shfl_xor_sync(0xffffffffu, s, o);
    if (lane == 0) (t ? g_k2 : g_q2)[rr] = s;
}

// ---------------- main GEMM: S = 2QK^T - q2 - k2 -> co, + BN1 stats ----------------
// CTA 128x128, warp tile 32x64 (4x2), k-chunk 32 double-buffered via cp.async, 2 CTAs/SM.
__global__ void __launch_bounds__(256, 2) gemm_kernel(const float* __restrict__ Q,
                                                      const float* __restrict__ K,
                                                      float* __restrict__ co) {
    extern __shared__ float sm[];
    __shared__ float q2s[128], k2s[128];
    __shared__ double rs[8], rq[8];

    int bh = blockIdx.z; int b = bh / Hn, h = bh % Hn;
    int bi0 = blockIdx.y*128, bj0 = blockIdx.x*128;
    const float* Qb = Q + (size_t)b*Ln*Dn + h*DHn;
    const float* Kb = K + (size_t)b*Ln*Dn + h*DHn;
    int tid = threadIdx.x, warp = tid >> 5, lane = tid & 31;

    if (tid < 128) {
        q2s[tid] = g_q2[bh*Ln + bi0 + tid];
        k2s[tid] = g_k2[bh*Ln + bj0 + tid];
    }

    uint32_t smem_base = (uint32_t)__cvta_generic_to_shared(sm);

    auto issue = [&](int c, int s) {
        #pragma unroll
        for (int i = 0; i < 4; i++) {
            int f = tid + i*256;            // 1024 float4 per tile
            int row = f >> 3, c4 = f & 7;
            const float* ga = Qb + (size_t)(bi0 + row)*Dn + c*KC + c4*4;
            cp_async16(smem_base + (uint32_t)(s*STAGE_F + row*CHLD + c4*4)*4u, ga);
            const float* gb = Kb + (size_t)(bj0 + row)*Dn + c*KC + c4*4;
            cp_async16(smem_base + (uint32_t)(s*STAGE_F + 128*CHLD + row*CHLD + c4*4)*4u, gb);
        }
    };

    int wm = warp & 3, wn = warp >> 2;
    wmma::fragment<wmma::accumulator, 16,16,8, float> acc[2][4];
    #pragma unroll
    for (int m = 0; m < 2; m++)
        #pragma unroll
        for (int n = 0; n < 4; n++) wmma::fill_fragment(acc[m][n], 0.f);

    auto compute = [&](int s) {
        const float* As = sm + s*STAGE_F;
        const float* Bs = As + 128*CHLD;
        #pragma unroll
        for (int k = 0; k < KC; k += 8) {
            wmma::fragment<wmma::matrix_a, 16,16,8, wmma::precision::tf32, wmma::row_major> af[2];
            wmma::fragment<wmma::matrix_b, 16,16,8, wmma::precision::tf32, wmma::col_major> bf[4];
            #pragma unroll
            for (int m = 0; m < 2; m++)
                wmma::load_matrix_sync(af[m], As + (wm*32 + m*16)*CHLD + k, CHLD);
            #pragma unroll
            for (int n = 0; n < 4; n++)
                wmma::load_matrix_sync(bf[n], Bs + (wn*64 + n*16)*CHLD + k, CHLD);
            #pragma unroll
            for (int m = 0; m < 2; m++)
                #pragma unroll
                for (int n = 0; n < 4; n++)
                    wmma::mma_sync(acc[m][n], af[m], bf[n], acc[m][n]);
        }
    };

    issue(0, 0); CP_COMMIT();
    issue(1, 1); CP_COMMIT();
    CP_WAIT(1); __syncthreads();        // chunk0 ready (also covers q2s/k2s)
    compute(0);
    __syncthreads();
    issue(2, 0); CP_COMMIT();
    CP_WAIT(1); __syncthreads();        // chunk1 ready
    compute(1);
    __syncthreads();
    issue(3, 1); CP_COMMIT();
    CP_WAIT(1); __syncthreads();        // chunk2 ready
    compute(0);
    __syncthreads();
    CP_WAIT(0); __syncthreads();        // chunk3 ready
    compute(1);
    __syncthreads();                    // done reading stage 1 before Cs overwrite

    // stage accumulators to smem (Cs aliases pipeline smem: 128*CLD*4 = 67.6KB <= 72KB)
    float* Cs = sm;
    #pragma unroll
    for (int m = 0; m < 2; m++)
        #pragma unroll
        for (int n = 0; n < 4; n++)
            wmma::store_matrix_sync(Cs + (wm*32 + m*16)*CLD + wn*64 + n*16, acc[m][n], CLD,
                                    wmma::mem_row_major);
    __syncthreads();

    // epilogue: s = 2c - q2 - k2, raw write to co, stats
    float lsum = 0.f, lsq = 0.f;
    #pragma unroll
    for (int i = 0; i < 16; i++) {
        int f = tid + i*256;            // 4096 float4
        int r = f >> 5, c4 = f & 31;
        float4 c = *(const float4*)&Cs[r*CLD + c4*4];
        float q2v = q2s[r];
        float4 s4;
        s4.x = 2.f*c.x - q2v - k2s[c4*4+0];
        s4.y = 2.f*c.y - q2v - k2s[c4*4+1];
        s4.z = 2.f*c.z - q2v - k2s[c4*4+2];
        s4.w = 2.f*c.w - q2v - k2s[c4*4+3];
        *(float4*)(co + ((size_t)(bh*Ln + bi0 + r))*Ln + bj0 + c4*4) = s4;
        lsum += s4.x + s4.y + s4.z + s4.w;
        lsq  += s4.x*s4.x + s4.y*s4.y + s4.z*s4.z + s4.w*s4.w;
    }
    double ds = (double)lsum, dq = (double)lsq;
    #pragma unroll
    for (int o = 16; o; o >>= 1) {
        ds += __shfl_xor_sync(0xffffffffu, ds, o);
        dq += __shfl_xor_sync(0xffffffffu, dq, o);
    }
    if (lane == 0) { rs[warp] = ds; rq[warp] = dq; }
    __syncthreads();
    if (warp == 0) {
        ds = (lane < 8) ? rs[lane] : 0.0;
        dq = (lane < 8) ? rq[lane] : 0.0;
        #pragma unroll
        for (int o = 4; o; o >>= 1) {
            ds += __shfl_xor_sync(0xffffffffu, ds, o);
            dq += __shfl_xor_sync(0xffffffffu, dq, o);
        }
        if (lane == 0) { atomicAdd(&g_sum1[h], ds); atomicAdd(&g_sumsq1[h], dq); }
    }
}

// ---------------- BN1 stats finalize ----------------
__global__ void stats1_kernel(const float* __restrict__ g1, const float* __restrict__ b1) {
    int h = threadIdx.x;
    if (h < Hn) {
        double n = (double)Bn*Ln*Ln;
        double m = g_sum1[h]/n;
        double var = g_sumsq1[h]/n - m*m;
        float rstd = (float)rsqrt(var + (double)EPSf);
        g_scale1[h] = g1[h]*rstd;
        g_shift1[h] = b1[h] - (float)m*rstd*g1[h];
    }
}

// ---------------- normalize + mask(0) + softmax (in place) + column sums ----------------
__global__ void __launch_bounds__(512) softmax_kernel(float* __restrict__ co) {
    __shared__ float colsum[Ln];
    __shared__ unsigned char sval[Ln];
    int bh = blockIdx.x >> 6;
    int rb = blockIdx.x & 63;
    int b = bh / Hn, h = bh % Hn;
    int tid = threadIdx.x, warp = tid >> 5, lane = tid & 31;
    for (int j = tid; j < Ln; j += 512) { colsum[j] = 0.f; sval[j] = g_valid[b*Ln + j]; }
    __syncthreads();

    int i = rb*16 + warp;
    bool rowvalid = sval[i] != 0;
    float scale = g_scale1[h], shift = g_shift1[h];
    float4* Sr = (float4*)(co + ((size_t)bh*Ln + i)*Ln);

    float v[32];
    float mx = -1e30f;
    #pragma unroll
    for (int c = 0; c < 8; c++) {
        float4 x = Sr[c*32 + lane];
        int j0 = c*128 + lane*4;
        float a0 = (rowvalid && sval[j0+0]) ? x.x*scale + shift : 0.f;
        float a1 = (rowvalid && sval[j0+1]) ? x.y*scale + shift : 0.f;
        float a2 = (rowvalid && sval[j0+2]) ? x.z*scale + shift : 0.f;
        float a3 = (rowvalid && sval[j0+3]) ? x.w*scale + shift : 0.f;
        v[c*4+0]=a0; v[c*4+1]=a1; v[c*4+2]=a2; v[c*4+3]=a3;
        mx = fmaxf(mx, fmaxf(fmaxf(a0,a1), fmaxf(a2,a3)));
    }
    #pragma unroll
    for (int o = 16; o; o >>= 1) mx = fmaxf(mx, __shfl_xor_sync(0xffffffffu, mx, o));
    float sum = 0.f;
    #pragma unroll
    for (int t = 0; t < 32; t++) { float e = __expf(v[t] - mx); v[t] = e; sum += e; }
    #pragma unroll
    for (int o = 16; o; o >>= 1) sum += __shfl_xor_sync(0xffffffffu, sum, o);
    float inv = 1.0f / sum;

    #pragma unroll
    for (int c = 0; c < 8; c++) {
        int j0 = c*128 + lane*4;
        float4 o4;
        o4.x = v[c*4+0]*inv; o4.y = v[c*4+1]*inv; o4.z = v[c*4+2]*inv; o4.w = v[c*4+3]*inv;
        Sr[c*32 + lane] = o4;
        atomicAdd(&colsum[j0+0], o4.x);
        atomicAdd(&colsum[j0+1], o4.y);
        atomicAdd(&colsum[j0+2], o4.z);
        atomicAdd(&colsum[j0+3], o4.w);
    }
    __syncthreads();
    for (int j = tid; j < Ln; j += 512) atomicAdd(&g_w[bh*Ln + j], colsum[j]);
}

// ---------------- BN2 stats ----------------
__global__ void stats2_kernel(const float* __restrict__ g2, const float* __restrict__ b2) {
    int h = blockIdx.x;
    int tid = threadIdx.x;
    float ls = 0.f, lq = 0.f;
    for (int b = 0; b < Bn; b++) {
        const float* wp = g_w + (b*Hn + h)*Ln;
        for (int j = tid; j < Ln; j += 256) { float x = wp[j]; ls += x; lq += x*x; }
    }
    double ds = (double)ls, dq = (double)lq;
    #pragma unroll
    for (int o = 16; o; o >>= 1) {
        ds += __shfl_xor_sync(0xffffffffu, ds, o);
        dq += __shfl_xor_sync(0xffffffffu, dq, o);
    }
    __shared__ double rs[8], rq[8];
    int warp = tid >> 5, lane = tid & 31;
    if (lane == 0) { rs[warp] = ds; rq[warp] = dq; }
    __syncthreads();
    if (tid == 0) {
        double S = 0.0, Q2 = 0.0;
        for (int wgi = 0; wgi < 8; wgi++) { S += rs[wgi]; Q2 += rq[wgi]; }
        double n = (double)Bn*Ln;
        double m = S/n;
        double var = Q2/n - m*m;
        float rstd = (float)rsqrt(var + (double)EPSf);
        g_scale2[h] = g2[h]*rstd;
        g_shift2[h] = b2[h] - (float)m*rstd*g2[h];
    }
}

// ---------------- posterior gate ----------------
__global__ void gate_kernel(const float* __restrict__ Wp, const float* __restrict__ bp) {
    int idx = blockIdx.x*blockDim.x + threadIdx.x;
    if (idx >= Bn*Ln) return;
    int b = idx >> 10, l = idx & (Ln-1);
    float z0 = bp[0], z1 = bp[1];
    #pragma unroll
    for (int h = 0; h < Hn; h++) {
        float wn = g_w[(b*Hn + h)*Ln + l]*g_scale2[h] + g_shift2[h];
        z0 += Wp[h]      * wn;
        z1 += Wp[Hn + h] * wn;
    }
    float d = z1 - z0;
    g_p[idx] = 1.f/(1.f + __expf(d));
}

// ---------------- final masked softmax ----------------
__global__ void final_kernel(float* __restrict__ out) {
    int b = blockIdx.x, l = threadIdx.x;
    __shared__ float redm[32], redsum[32], bc[2];
    const float NEG_INF = __int_as_float(0xff800000);
    float x = g_valid[b*Ln + l] ? g_p[b*Ln + l] : NEG_INF;
    int warp = l >> 5, lane = l & 31;
    float m = x;
    #pragma unroll
    for (int o = 16; o; o >>= 1) m = fmaxf(m, __shfl_xor_sync(0xffffffffu, m, o));
    if (lane == 0) redm[warp] = m;
    __syncthreads();
    if (warp == 0) {
        m = redm[lane];
        #pragma unroll
        for (int o = 16; o; o >>= 1) m = fmaxf(m, __shfl_xor_sync(0xffffffffu, m, o));
        if (lane == 0) bc[0] = m;
    }
    __syncthreads();
    m = bc[0];
    float e = __expf(x - m);
    float s = e;
    #pragma unroll
    for (int o = 16; o; o >>= 1) s += __shfl_xor_sync(0xffffffffu, s, o);
    if (lane == 0) redsum[warp] = s;
    __syncthreads();
    if (warp == 0) {
        s = redsum[lane];
        #pragma unroll
        for (int o = 16; o; o >>= 1) s += __shfl_xor_sync(0xffffffffu, s, o);
        if (lane == 0) bc[1] = s;
    }
    __syncthreads();
    out[OFF_W + b*Ln + l] = e / bc[1];
}

// ---------------- launch ----------------
extern "C" void kernel_launch(void* const* d_in, const int* in_sizes, int n_in,
                              void* d_out, int out_size) {
    const float* Q  = (const float*)d_in[0];
    const float* K  = (const float*)d_in[1];
    const float* V  = (const float*)d_in[2];
    const unsigned int* bx = (const unsigned int*)d_in[4];
    const float* g1 = (const float*)d_in[5];
    const float* b1 = (const float*)d_in[6];
    const float* g2 = (const float*)d_in[7];
    const float* b2 = (const float*)d_in[8];
    const float* Wp = (const float*)d_in[9];
    const float* bp = (const float*)d_in[10];
    float* out = (float*)d_out;

    const int SMG = STAGE_F*2*4;   // 73728 bytes
    cudaFuncSetAttribute(gemm_kernel, cudaFuncAttributeMaxDynamicSharedMemorySize, SMG);

    zero_kernel<<<(BHn*Ln + 255)/256, 256>>>();
    mask_kernel<<<1, 256>>>(bx);
    vout_kernel<<<(BHn*Ln*DHn/4 + 255)/256, 256>>>(V, out);
    sq_kernel<<<(2*BHn*Ln*32 + 255)/256, 256>>>(Q, K);
    gemm_kernel<<<dim3(Ln/128, Ln/128, BHn), 256, SMG>>>(Q, K, out);
    stats1_kernel<<<1, 32>>>(g1, b1);
    softmax_kernel<<<BHn*(Ln/16), 512>>>(out);
    stats2_kernel<<<Hn, 256>>>(g2, b2);
    gate_kernel<<<(Bn*Ln + 255)/256, 256>>>(Wp, bp);
    final_kernel<<<Bn, Ln>>>(out);
}

// round 5
// speedup vs baseline: 1.1354x; 1.1354x over previous
#include <cuda_runtime.h>
#include <mma.h>
#include <cstdint>

using namespace nvcuda;

#define Bn  4
#define Ln  1024
#define Dn  768
#define Hn  6
#define DHn 128
#define BHn (Bn*Hn)
#define EPSf 1e-5f
#define GLD 132   /* smem leading dim: 128 + 4 pad */

#define OFF_CO 0
#define OFF_W  (BHn*Ln*Ln)          /* 25165824 */
#define OFF_V  (OFF_W + Bn*Ln)      /* 25169920 */

// ---------------- scratch ----------------
__device__ float  g_q2[BHn*Ln];
__device__ float  g_k2[BHn*Ln];
__device__ double g_sum1[Hn];
__device__ double g_sumsq1[Hn];
__device__ float  g_scale1[Hn];
__device__ float  g_shift1[Hn];
__device__ float  g_w[BHn*Ln];
__device__ float  g_scale2[Hn];
__device__ float  g_shift2[Hn];
__device__ float  g_p[Bn*Ln];
__device__ unsigned char g_valid[Bn*Ln];

// ---------------- zero accumulators ----------------
__global__ void zero_kernel() {
    int idx = blockIdx.x*blockDim.x + threadIdx.x;
    if (idx < BHn*Ln) g_w[idx] = 0.f;
    if (idx < Hn) { g_sum1[idx] = 0.0; g_sumsq1[idx] = 0.0; }
}

// ---------------- mask: derive valid[] from bx_packed with dtype sniff ----------------
__global__ void mask_kernel(const unsigned int* w) {
    __shared__ int s_float, s_byte;
    if (threadIdx.x == 0) { s_float = 0; s_byte = 0; }
    __syncthreads();
    for (int i = threadIdx.x; i < (Bn*Ln)/4; i += blockDim.x) {
        unsigned v = w[i];
        if (v == 0x3f800000u) atomicOr(&s_float, 1);
        else if (v > 1u)      atomicOr(&s_byte, 1);
    }
    __syncthreads();
    int byte_mode = (!s_float) && s_byte;
    const unsigned char* bytes = (const unsigned char*)w;
    for (int i = threadIdx.x; i < Bn*Ln; i += blockDim.x) {
        bool padded = byte_mode ? (bytes[i] != 0) : (w[i] != 0u);
        g_valid[i] = padded ? 0 : 1;
    }
}

// ---------------- Vh output: transpose copy ----------------
__global__ void vout_kernel(const float* __restrict__ V, float* __restrict__ out) {
    int idx = blockIdx.x*blockDim.x + threadIdx.x;
    if (idx >= BHn*Ln*DHn/4) return;
    int d4 = idx & 31;
    int l  = (idx >> 5) & (Ln-1);
    int h  = (idx >> 15) % Hn;
    int b  = idx / (32*Ln*Hn);
    float4 v = *(const float4*)(V + ((size_t)(b*Ln + l))*Dn + h*DHn + d4*4);
    ((float4*)(out + OFF_V))[idx] = v;
}

// ---------------- squared norms per head-row (fp32 exact) ----------------
__global__ void sq_kernel(const float* __restrict__ Q, const float* __restrict__ K) {
    int warp = (blockIdx.x*blockDim.x + threadIdx.x) >> 5;
    int lane = threadIdx.x & 31;
    if (warp >= 2*BHn*Ln) return;
    int t  = warp / (BHn*Ln);
    int rr = warp % (BHn*Ln);
    int bh = rr / Ln, i = rr % Ln;
    int b = bh / Hn, h = bh % Hn;
    const float* src = (t ? K : Q) + ((size_t)(b*Ln + i))*Dn + h*DHn;
    float4 x = ((const float4*)src)[lane];
    float s = x.x*x.x + x.y*x.y + x.z*x.z + x.w*x.w;
    #pragma unroll
    for (int o = 16; o; o >>= 1) s += __shfl_xor_sync(0xffffffffu, s, o);
    if (lane == 0) (t ? g_k2 : g_q2)[rr] = s;
}

// ---------------- main GEMM: S = 2QK^T - q2 - k2 -> co, + BN1 stats ----------------
// CTA 256x128, 512 threads, warp tile 32x64 (8x2 warp grid), K=128 resident in smem.
__global__ void __launch_bounds__(512, 1) gemm_kernel(const float* __restrict__ Q,
                                                      const float* __restrict__ K,
                                                      float* __restrict__ co) {
    extern __shared__ float sm[];
    float* As = sm;                  // 256 x GLD (tf32)
    float* Bs = sm + 256*GLD;        // 128 x GLD (tf32)
    float* Cs = sm;                  // alias after mma
    __shared__ float q2s[256], k2s[128];
    __shared__ double rs[16], rq[16];

    int bh = blockIdx.z; int b = bh / Hn, h = bh % Hn;
    int bi0 = blockIdx.y*256, bj0 = blockIdx.x*128;
    const float* Qb = Q + (size_t)b*Ln*Dn + h*DHn;
    const float* Kb = K + (size_t)b*Ln*Dn + h*DHn;
    int tid = threadIdx.x, warp = tid >> 5, lane = tid & 31;

    if (tid < 256) q2s[tid] = g_q2[bh*Ln + bi0 + tid];
    else if (tid < 384) k2s[tid - 256] = g_k2[bh*Ln + bj0 + tid - 256];

    // load A (256x128) + B (128x128) as tf32
    #pragma unroll
    for (int i = 0; i < 16; i++) {
        int t = tid + i*512;            // 8192 float4 for A
        int r = t >> 5, c = t & 31;
        float4 q = *(const float4*)(Qb + (size_t)(bi0 + r)*Dn + c*4);
        As[r*GLD + c*4 + 0] = wmma::__float_to_tf32(q.x);
        As[r*GLD + c*4 + 1] = wmma::__float_to_tf32(q.y);
        As[r*GLD + c*4 + 2] = wmma::__float_to_tf32(q.z);
        As[r*GLD + c*4 + 3] = wmma::__float_to_tf32(q.w);
    }
    #pragma unroll
    for (int i = 0; i < 8; i++) {
        int t = tid + i*512;            // 4096 float4 for B
        int r = t >> 5, c = t & 31;
        float4 k = *(const float4*)(Kb + (size_t)(bj0 + r)*Dn + c*4);
        Bs[r*GLD + c*4 + 0] = wmma::__float_to_tf32(k.x);
        Bs[r*GLD + c*4 + 1] = wmma::__float_to_tf32(k.y);
        Bs[r*GLD + c*4 + 2] = wmma::__float_to_tf32(k.z);
        Bs[r*GLD + c*4 + 3] = wmma::__float_to_tf32(k.w);
    }
    __syncthreads();

    // warp grid: 8 (M) x 2 (N); warp tile 32x64
    int wm = warp & 7, wn = warp >> 3;
    wmma::fragment<wmma::accumulator, 16,16,8, float> acc[2][4];
    #pragma unroll
    for (int m = 0; m < 2; m++)
        #pragma unroll
        for (int n = 0; n < 4; n++) wmma::fill_fragment(acc[m][n], 0.f);
    #pragma unroll
    for (int k = 0; k < 128; k += 8) {
        wmma::fragment<wmma::matrix_a, 16,16,8, wmma::precision::tf32, wmma::row_major> af[2];
        wmma::fragment<wmma::matrix_b, 16,16,8, wmma::precision::tf32, wmma::col_major> bf[4];
        #pragma unroll
        for (int m = 0; m < 2; m++)
            wmma::load_matrix_sync(af[m], As + (wm*32 + m*16)*GLD + k, GLD);
        #pragma unroll
        for (int n = 0; n < 4; n++)
            wmma::load_matrix_sync(bf[n], Bs + (wn*64 + n*16)*GLD + k, GLD);
        #pragma unroll
        for (int m = 0; m < 2; m++)
            #pragma unroll
            for (int n = 0; n < 4; n++)
                wmma::mma_sync(acc[m][n], af[m], bf[n], acc[m][n]);
    }
    __syncthreads();
    #pragma unroll
    for (int m = 0; m < 2; m++)
        #pragma unroll
        for (int n = 0; n < 4; n++)
            wmma::store_matrix_sync(Cs + (wm*32 + m*16)*GLD + wn*64 + n*16, acc[m][n], GLD,
                                    wmma::mem_row_major);
    __syncthreads();

    // epilogue: s = 2c - q2 - k2, raw write to co, stats
    float lsum = 0.f, lsq = 0.f;
    #pragma unroll
    for (int i = 0; i < 16; i++) {
        int f = tid + i*512;            // 8192 float4
        int r = f >> 5, c4 = f & 31;
        float4 c = *(const float4*)&Cs[r*GLD + c4*4];
        float q2v = q2s[r];
        float4 s4;
        s4.x = 2.f*c.x - q2v - k2s[c4*4+0];
        s4.y = 2.f*c.y - q2v - k2s[c4*4+1];
        s4.z = 2.f*c.z - q2v - k2s[c4*4+2];
        s4.w = 2.f*c.w - q2v - k2s[c4*4+3];
        *(float4*)(co + ((size_t)(bh*Ln + bi0 + r))*Ln + bj0 + c4*4) = s4;
        lsum += s4.x + s4.y + s4.z + s4.w;
        lsq  += s4.x*s4.x + s4.y*s4.y + s4.z*s4.z + s4.w*s4.w;
    }
    double ds = (double)lsum, dq = (double)lsq;
    #pragma unroll
    for (int o = 16; o; o >>= 1) {
        ds += __shfl_xor_sync(0xffffffffu, ds, o);
        dq += __shfl_xor_sync(0xffffffffu, dq, o);
    }
    if (lane == 0) { rs[warp] = ds; rq[warp] = dq; }
    __syncthreads();
    if (warp == 0) {
        ds = (lane < 16) ? rs[lane] : 0.0;
        dq = (lane < 16) ? rq[lane] : 0.0;
        #pragma unroll
        for (int o = 8; o; o >>= 1) {
            ds += __shfl_xor_sync(0xffffffffu, ds, o);
            dq += __shfl_xor_sync(0xffffffffu, dq, o);
        }
        if (lane == 0) { atomicAdd(&g_sum1[h], ds); atomicAdd(&g_sumsq1[h], dq); }
    }
}

// ---------------- BN1 stats finalize ----------------
__global__ void stats1_kernel(const float* __restrict__ g1, const float* __restrict__ b1) {
    int h = threadIdx.x;
    if (h < Hn) {
        double n = (double)Bn*Ln*Ln;
        double m = g_sum1[h]/n;
        double var = g_sumsq1[h]/n - m*m;
        float rstd = (float)rsqrt(var + (double)EPSf);
        g_scale1[h] = g1[h]*rstd;
        g_shift1[h] = b1[h] - (float)m*rstd*g1[h];
    }
}

// ---------------- normalize + mask(0) + softmax (in place) + column sums ----------------
__global__ void __launch_bounds__(512) softmax_kernel(float* __restrict__ co) {
    __shared__ float colsum[Ln];
    __shared__ unsigned char sval[Ln];
    int bh = blockIdx.x >> 6;
    int rb = blockIdx.x & 63;
    int b = bh / Hn, h = bh % Hn;
    int tid = threadIdx.x, warp = tid >> 5, lane = tid & 31;
    for (int j = tid; j < Ln; j += 512) { colsum[j] = 0.f; sval[j] = g_valid[b*Ln + j]; }
    __syncthreads();

    int i = rb*16 + warp;
    bool rowvalid = sval[i] != 0;
    float scale = g_scale1[h], shift = g_shift1[h];
    float4* Sr = (float4*)(co + ((size_t)bh*Ln + i)*Ln);

    float v[32];
    float mx = -1e30f;
    #pragma unroll
    for (int c = 0; c < 8; c++) {
        float4 x = Sr[c*32 + lane];
        int j0 = c*128 + lane*4;
        float a0 = (rowvalid && sval[j0+0]) ? x.x*scale + shift : 0.f;
        float a1 = (rowvalid && sval[j0+1]) ? x.y*scale + shift : 0.f;
        float a2 = (rowvalid && sval[j0+2]) ? x.z*scale + shift : 0.f;
        float a3 = (rowvalid && sval[j0+3]) ? x.w*scale + shift : 0.f;
        v[c*4+0]=a0; v[c*4+1]=a1; v[c*4+2]=a2; v[c*4+3]=a3;
        mx = fmaxf(mx, fmaxf(fmaxf(a0,a1), fmaxf(a2,a3)));
    }
    #pragma unroll
    for (int o = 16; o; o >>= 1) mx = fmaxf(mx, __shfl_xor_sync(0xffffffffu, mx, o));
    float sum = 0.f;
    #pragma unroll
    for (int t = 0; t < 32; t++) { float e = __expf(v[t] - mx); v[t] = e; sum += e; }
    #pragma unroll
    for (int o = 16; o; o >>= 1) sum += __shfl_xor_sync(0xffffffffu, sum, o);
    float inv = 1.0f / sum;

    #pragma unroll
    for (int c = 0; c < 8; c++) {
        int j0 = c*128 + lane*4;
        float4 o4;
        o4.x = v[c*4+0]*inv; o4.y = v[c*4+1]*inv; o4.z = v[c*4+2]*inv; o4.w = v[c*4+3]*inv;
        Sr[c*32 + lane] = o4;
        atomicAdd(&colsum[j0+0], o4.x);
        atomicAdd(&colsum[j0+1], o4.y);
        atomicAdd(&colsum[j0+2], o4.z);
        atomicAdd(&colsum[j0+3], o4.w);
    }
    __syncthreads();
    for (int j = tid; j < Ln; j += 512) atomicAdd(&g_w[bh*Ln + j], colsum[j]);
}

// ---------------- BN2 stats ----------------
__global__ void stats2_kernel(const float* __restrict__ g2, const float* __restrict__ b2) {
    int h = blockIdx.x;
    int tid = threadIdx.x;
    float ls = 0.f, lq = 0.f;
    for (int b = 0; b < Bn; b++) {
        const float* wp = g_w + (b*Hn + h)*Ln;
        for (int j = tid; j < Ln; j += 256) { float x = wp[j]; ls += x; lq += x*x; }
    }
    double ds = (double)ls, dq = (double)lq;
    #pragma unroll
    for (int o = 16; o; o >>= 1) {
        ds += __shfl_xor_sync(0xffffffffu, ds, o);
        dq += __shfl_xor_sync(0xffffffffu, dq, o);
    }
    __shared__ double rs[8], rq[8];
    int warp = tid >> 5, lane = tid & 31;
    if (lane == 0) { rs[warp] = ds; rq[warp] = dq; }
    __syncthreads();
    if (tid == 0) {
        double S = 0.0, Q2 = 0.0;
        for (int wgi = 0; wgi < 8; wgi++) { S += rs[wgi]; Q2 += rq[wgi]; }
        double n = (double)Bn*Ln;
        double m = S/n;
        double var = Q2/n - m*m;
        float rstd = (float)rsqrt(var + (double)EPSf);
        g_scale2[h] = g2[h]*rstd;
        g_shift2[h] = b2[h] - (float)m*rstd*g2[h];
    }
}

// ---------------- posterior gate ----------------
__global__ void gate_kernel(const float* __restrict__ Wp, const float* __restrict__ bp) {
    int idx = blockIdx.x*blockDim.x + threadIdx.x;
    if (idx >= Bn*Ln) return;
    int b = idx >> 10, l = idx & (Ln-1);
    float z0 = bp[0], z1 = bp[1];
    #pragma unroll
    for (int h = 0; h < Hn; h++) {
        float wn = g_w[(b*Hn + h)*Ln + l]*g_scale2[h] + g_shift2[h];
        z0 += Wp[h]      * wn;
        z1 += Wp[Hn + h] * wn;
    }
    float d = z1 - z0;
    g_p[idx] = 1.f/(1.f + __expf(d));
}

// ---------------- final masked softmax ----------------
__global__ void final_kernel(float* __restrict__ out) {
    int b = blockIdx.x, l = threadIdx.x;
    __shared__ float redm[32], redsum[32], bc[2];
    const float NEG_INF = __int_as_float(0xff800000);
    float x = g_valid[b*Ln + l] ? g_p[b*Ln + l] : NEG_INF;
    int warp = l >> 5, lane = l & 31;
    float m = x;
    #pragma unroll
    for (int o = 16; o; o >>= 1) m = fmaxf(m, __shfl_xor_sync(0xffffffffu, m, o));
    if (lane == 0) redm[warp] = m;
    __syncthreads();
    if (warp == 0) {
        m = redm[lane];
        #pragma unroll
        for (int o = 16; o; o >>= 1) m = fmaxf(m, __shfl_xor_sync(0xffffffffu, m, o));
        if (lane == 0) bc[0] = m;
    }
    __syncthreads();
    m = bc[0];
    float e = __expf(x - m);
    float s = e;
    #pragma unroll
    for (int o = 16; o; o >>= 1) s += __shfl_xor_sync(0xffffffffu, s, o);
    if (lane == 0) redsum[warp] = s;
    __syncthreads();
    if (warp == 0) {
        s = redsum[lane];
        #pragma unroll
        for (int o = 16; o; o >>= 1) s += __shfl_xor_sync(0xffffffffu, s, o);
        if (lane == 0) bc[1] = s;
    }
    __syncthreads();
    out[OFF_W + b*Ln + l] = e / bc[1];
}

// ---------------- launch ----------------
extern "C" void kernel_launch(void* const* d_in, const int* in_sizes, int n_in,
                              void* d_out, int out_size) {
    const float* Q  = (const float*)d_in[0];
    const float* K  = (const float*)d_in[1];
    const float* V  = (const float*)d_in[2];
    const unsigned int* bx = (const unsigned int*)d_in[4];
    const float* g1 = (const float*)d_in[5];
    const float* b1 = (const float*)d_in[6];
    const float* g2 = (const float*)d_in[7];
    const float* b2 = (const float*)d_in[8];
    const float* Wp = (const float*)d_in[9];
    const float* bp = (const float*)d_in[10];
    float* out = (float*)d_out;

    const int SMG = (256 + 128)*GLD*4;   // 202752
    cudaFuncSetAttribute(gemm_kernel, cudaFuncAttributeMaxDynamicSharedMemorySize, SMG);

    zero_kernel<<<(BHn*Ln + 255)/256, 256>>>();
    mask_kernel<<<1, 256>>>(bx);
    vout_kernel<<<(BHn*Ln*DHn/4 + 255)/256, 256>>>(V, out);
    sq_kernel<<<(2*BHn*Ln*32 + 255)/256, 256>>>(Q, K);
    gemm_kernel<<<dim3(Ln/128, Ln/256, BHn), 512, SMG>>>(Q, K, out);
    stats1_kernel<<<1, 32>>>(g1, b1);
    softmax_kernel<<<BHn*(Ln/16), 512>>>(out);
    stats2_kernel<<<Hn, 256>>>(g2, b2);
    gate_kernel<<<(Bn*Ln + 255)/256, 256>>>(Wp, bp);
    final_kernel<<<Bn, Ln>>>(out);
}

// round 7
// speedup vs baseline: 2.4400x; 2.1491x over previous
#include <cuda_runtime.h>
#include <mma.h>
#include <cuda_fp16.h>
#include <cstdint>

using namespace nvcuda;

#define Bn  4
#define Ln  1024
#define Dn  768
#define Hn  6
#define DHn 128
#define BHn (Bn*Hn)
#define EPSf 1e-5f
#define GLDH 136   /* half leading dim: 128 + 8 (16B pad, conflict-free ldmatrix) */
#define CLD  132   /* epilogue float staging leading dim */

#define OFF_CO 0
#define OFF_W  (BHn*Ln*Ln)          /* 25165824 */
#define OFF_V  (OFF_W + Bn*Ln)      /* 25169920 */

// ---------------- scratch ----------------
__device__ float  g_q2[BHn*Ln];
__device__ float  g_k2[BHn*Ln];
__device__ double g_sum1[Hn];
__device__ double g_sumsq1[Hn];
__device__ float  g_scale1[Hn];
__device__ float  g_shift1[Hn];
__device__ float  g_w[BHn*Ln];
__device__ float  g_scale2[Hn];
__device__ float  g_shift2[Hn];
__device__ float  g_p[Bn*Ln];
__device__ unsigned char g_valid[Bn*Ln];

// ---------------- zero accumulators ----------------
__global__ void zero_kernel() {
    int idx = blockIdx.x*blockDim.x + threadIdx.x;
    if (idx < BHn*Ln) g_w[idx] = 0.f;
    if (idx < Hn) { g_sum1[idx] = 0.0; g_sumsq1[idx] = 0.0; }
}

// ---------------- mask: derive valid[] from bx_packed with dtype sniff ----------------
__global__ void mask_kernel(const unsigned int* w) {
    __shared__ int s_float, s_byte;
    if (threadIdx.x == 0) { s_float = 0; s_byte = 0; }
    __syncthreads();
    for (int i = threadIdx.x; i < (Bn*Ln)/4; i += blockDim.x) {
        unsigned v = w[i];
        if (v == 0x3f800000u) atomicOr(&s_float, 1);
        else if (v > 1u)      atomicOr(&s_byte, 1);
    }
    __syncthreads();
    int byte_mode = (!s_float) && s_byte;
    const unsigned char* bytes = (const unsigned char*)w;
    for (int i = threadIdx.x; i < Bn*Ln; i += blockDim.x) {
        bool padded = byte_mode ? (bytes[i] != 0) : (w[i] != 0u);
        g_valid[i] = padded ? 0 : 1;
    }
}

// ---------------- Vh output: transpose copy ----------------
__global__ void vout_kernel(const float* __restrict__ V, float* __restrict__ out) {
    int idx = blockIdx.x*blockDim.x + threadIdx.x;
    if (idx >= BHn*Ln*DHn/4) return;
    int d4 = idx & 31;
    int l  = (idx >> 5) & (Ln-1);
    int h  = (idx >> 15) % Hn;
    int b  = idx / (32*Ln*Hn);
    float4 v = *(const float4*)(V + ((size_t)(b*Ln + l))*Dn + h*DHn + d4*4);
    ((float4*)(out + OFF_V))[idx] = v;
}

// ---------------- squared norms per head-row (fp32 exact) ----------------
__global__ void sq_kernel(const float* __restrict__ Q, const float* __restrict__ K) {
    int warp = (blockIdx.x*blockDim.x + threadIdx.x) >> 5;
    int lane = threadIdx.x & 31;
    if (warp >= 2*BHn*Ln) return;
    int t  = warp / (BHn*Ln);
    int rr = warp % (BHn*Ln);
    int bh = rr / Ln, i = rr % Ln;
    int b = bh / Hn, h = bh % Hn;
    const float* src = (t ? K : Q) + ((size_t)(b*Ln + i))*Dn + h*DHn;
    float4 x = ((const float4*)src)[lane];
    float s = x.x*x.x + x.y*x.y + x.z*x.z + x.w*x.w;
    #pragma unroll
    for (int o = 16; o; o >>= 1) s += __shfl_xor_sync(0xffffffffu, s, o);
    if (lane == 0) (t ? g_k2 : g_q2)[rr] = s;
}

// ---------------- main GEMM (fp16 wmma): S = 2QK^T - q2 - k2 -> co, + BN1 stats ----------------
// CTA tile 256x128, warp tile 64x64 (4x2 warp grid), K=128 resident (half), m16n16k16.
__global__ void __launch_bounds__(256) gemm_kernel(const float* __restrict__ Q,
                                                   const float* __restrict__ K,
                                                   float* __restrict__ co) {
    extern __shared__ char smraw[];
    __half* As = (__half*)smraw;                    // 256 x GLDH
    __half* Bs = As + 256*GLDH;                     // 128 x GLDH
    float*  Cs = (float*)smraw;                     // alias after mma (256 x CLD)
    __shared__ float q2s[256], k2s[128];
    __shared__ double rs[8], rq[8];

    int bh = blockIdx.z; int b = bh / Hn, h = bh % Hn;
    int bi0 = blockIdx.y*256, bj0 = blockIdx.x*128;
    const float* Qb = Q + (size_t)b*Ln*Dn + h*DHn;
    const float* Kb = K + (size_t)b*Ln*Dn + h*DHn;
    int tid = threadIdx.x, warp = tid >> 5, lane = tid & 31;

    if (tid < 128) k2s[tid] = g_k2[bh*Ln + bj0 + tid];
    else q2s[tid - 128] = g_q2[bh*Ln + bi0 + tid - 128];
    if (tid < 128) q2s[128 + tid] = g_q2[bh*Ln + bi0 + 128 + tid];

    // load A (256x128) + B (128x128) as half
    #pragma unroll
    for (int i = 0; i < 32; i++) {
        int t = tid + i*256;            // 8192 float4 for A
        int r = t >> 5, c = t & 31;
        float4 q = *(const float4*)(Qb + (size_t)(bi0 + r)*Dn + c*4);
        half2 h01 = __floats2half2_rn(q.x, q.y);
        half2 h23 = __floats2half2_rn(q.z, q.w);
        *(half2*)&As[r*GLDH + c*4 + 0] = h01;
        *(half2*)&As[r*GLDH + c*4 + 2] = h23;
    }
    #pragma unroll
    for (int i = 0; i < 16; i++) {
        int t = tid + i*256;            // 4096 float4 for B
        int r = t >> 5, c = t & 31;
        float4 k = *(const float4*)(Kb + (size_t)(bj0 + r)*Dn + c*4);
        half2 h01 = __floats2half2_rn(k.x, k.y);
        half2 h23 = __floats2half2_rn(k.z, k.w);
        *(half2*)&Bs[r*GLDH + c*4 + 0] = h01;
        *(half2*)&Bs[r*GLDH + c*4 + 2] = h23;
    }
    __syncthreads();

    // warp grid: 4 (M) x 2 (N); warp tile 64x64; k-step 16
    int wm = warp & 3, wn = warp >> 2;
    wmma::fragment<wmma::accumulator, 16,16,16, float> acc[4][4];
    #pragma unroll
    for (int m = 0; m < 4; m++)
        #pragma unroll
        for (int n = 0; n < 4; n++) wmma::fill_fragment(acc[m][n], 0.f);
    #pragma unroll
    for (int k = 0; k < 128; k += 16) {
        wmma::fragment<wmma::matrix_a, 16,16,16, __half, wmma::row_major> af[4];
        wmma::fragment<wmma::matrix_b, 16,16,16, __half, wmma::col_major> bf[4];
        #pragma unroll
        for (int m = 0; m < 4; m++)
            wmma::load_matrix_sync(af[m], As + (wm*64 + m*16)*GLDH + k, GLDH);
        #pragma unroll
        for (int n = 0; n < 4; n++)
            wmma::load_matrix_sync(bf[n], Bs + (wn*64 + n*16)*GLDH + k, GLDH);
        #pragma unroll
        for (int m = 0; m < 4; m++)
            #pragma unroll
            for (int n = 0; n < 4; n++)
                wmma::mma_sync(acc[m][n], af[m], bf[n], acc[m][n]);
    }
    __syncthreads();
    #pragma unroll
    for (int m = 0; m < 4; m++)
        #pragma unroll
        for (int n = 0; n < 4; n++)
            wmma::store_matrix_sync(Cs + (wm*64 + m*16)*CLD + wn*64 + n*16, acc[m][n], CLD,
                                    wmma::mem_row_major);
    __syncthreads();

    // epilogue: s = 2c - q2 - k2, raw write to co, stats
    float lsum = 0.f, lsq = 0.f;
    #pragma unroll
    for (int i = 0; i < 32; i++) {
        int f = tid + i*256;            // 8192 float4
        int r = f >> 5, c4 = f & 31;
        float4 c = *(const float4*)&Cs[r*CLD + c4*4];
        float q2v = q2s[r];
        float4 s4;
        s4.x = 2.f*c.x - q2v - k2s[c4*4+0];
        s4.y = 2.f*c.y - q2v - k2s[c4*4+1];
        s4.z = 2.f*c.z - q2v - k2s[c4*4+2];
        s4.w = 2.f*c.w - q2v - k2s[c4*4+3];
        *(float4*)(co + ((size_t)(bh*Ln + bi0 + r))*Ln + bj0 + c4*4) = s4;
        lsum += s4.x + s4.y + s4.z + s4.w;
        lsq  += s4.x*s4.x + s4.y*s4.y + s4.z*s4.z + s4.w*s4.w;
    }
    double ds = (double)lsum, dq = (double)lsq;
    #pragma unroll
    for (int o = 16; o; o >>= 1) {
        ds += __shfl_xor_sync(0xffffffffu, ds, o);
        dq += __shfl_xor_sync(0xffffffffu, dq, o);
    }
    if (lane == 0) { rs[warp] = ds; rq[warp] = dq; }
    __syncthreads();
    if (warp == 0) {
        ds = (lane < 8) ? rs[lane] : 0.0;
        dq = (lane < 8) ? rq[lane] : 0.0;
        #pragma unroll
        for (int o = 4; o; o >>= 1) {
            ds += __shfl_xor_sync(0xffffffffu, ds, o);
            dq += __shfl_xor_sync(0xffffffffu, dq, o);
        }
        if (lane == 0) { atomicAdd(&g_sum1[h], ds); atomicAdd(&g_sumsq1[h], dq); }
    }
}

// ---------------- BN1 stats finalize ----------------
__global__ void stats1_kernel(const float* __restrict__ g1, const float* __restrict__ b1) {
    int h = threadIdx.x;
    if (h < Hn) {
        double n = (double)Bn*Ln*Ln;
        double m = g_sum1[h]/n;
        double var = g_sumsq1[h]/n - m*m;
        float rstd = (float)rsqrt(var + (double)EPSf);
        g_scale1[h] = g1[h]*rstd;
        g_shift1[h] = b1[h] - (float)m*rstd*g1[h];
    }
}

// ---------------- normalize + mask(0) + softmax (in place) + column sums ----------------
__global__ void __launch_bounds__(512) softmax_kernel(float* __restrict__ co) {
    __shared__ float colsum[Ln];
    __shared__ unsigned char sval[Ln];
    int bh = blockIdx.x >> 6;
    int rb = blockIdx.x & 63;
    int b = bh / Hn, h = bh % Hn;
    int tid = threadIdx.x, warp = tid >> 5, lane = tid & 31;
    for (int j = tid; j < Ln; j += 512) { colsum[j] = 0.f; sval[j] = g_valid[b*Ln + j]; }
    __syncthreads();

    int i = rb*16 + warp;
    bool rowvalid = sval[i] != 0;
    float scale = g_scale1[h], shift = g_shift1[h];
    float4* Sr = (float4*)(co + ((size_t)bh*Ln + i)*Ln);

    float v[32];
    float mx = -1e30f;
    #pragma unroll
    for (int c = 0; c < 8; c++) {
        float4 x = Sr[c*32 + lane];
        int j0 = c*128 + lane*4;
        float a0 = (rowvalid && sval[j0+0]) ? x.x*scale + shift : 0.f;
        float a1 = (rowvalid && sval[j0+1]) ? x.y*scale + shift : 0.f;
        float a2 = (rowvalid && sval[j0+2]) ? x.z*scale + shift : 0.f;
        float a3 = (rowvalid && sval[j0+3]) ? x.w*scale + shift : 0.f;
        v[c*4+0]=a0; v[c*4+1]=a1; v[c*4+2]=a2; v[c*4+3]=a3;
        mx = fmaxf(mx, fmaxf(fmaxf(a0,a1), fmaxf(a2,a3)));
    }
    #pragma unroll
    for (int o = 16; o; o >>= 1) mx = fmaxf(mx, __shfl_xor_sync(0xffffffffu, mx, o));
    float sum = 0.f;
    #pragma unroll
    for (int t = 0; t < 32; t++) { float e = __expf(v[t] - mx); v[t] = e; sum += e; }
    #pragma unroll
    for (int o = 16; o; o >>= 1) sum += __shfl_xor_sync(0xffffffffu, sum, o);
    float inv = 1.0f / sum;

    #pragma unroll
    for (int c = 0; c < 8; c++) {
        int j0 = c*128 + lane*4;
        float4 o4;
        o4.x = v[c*4+0]*inv; o4.y = v[c*4+1]*inv; o4.z = v[c*4+2]*inv; o4.w = v[c*4+3]*inv;
        Sr[c*32 + lane] = o4;
        atomicAdd(&colsum[j0+0], o4.x);
        atomicAdd(&colsum[j0+1], o4.y);
        atomicAdd(&colsum[j0+2], o4.z);
        atomicAdd(&colsum[j0+3], o4.w);
    }
    __syncthreads();
    for (int j = tid; j < Ln; j += 512) atomicAdd(&g_w[bh*Ln + j], colsum[j]);
}

// ---------------- BN2 stats ----------------
__global__ void stats2_kernel(const float* __restrict__ g2, const float* __restrict__ b2) {
    int h = blockIdx.x;
    int tid = threadIdx.x;
    float ls = 0.f, lq = 0.f;
    for (int b = 0; b < Bn; b++) {
        const float* wp = g_w + (b*Hn + h)*Ln;
        for (int j = tid; j < Ln; j += 256) { float x = wp[j]; ls += x; lq += x*x; }
    }
    double ds = (double)ls, dq = (double)lq;
    #pragma unroll
    for (int o = 16; o; o >>= 1) {
        ds += __shfl_xor_sync(0xffffffffu, ds, o);
        dq += __shfl_xor_sync(0xffffffffu, dq, o);
    }
    __shared__ double rs[8], rq[8];
    int warp = tid >> 5, lane = tid & 31;
    if (lane == 0) { rs[warp] = ds; rq[warp] = dq; }
    __syncthreads();
    if (tid == 0) {
        double S = 0.0, Q2 = 0.0;
        for (int wgi = 0; wgi < 8; wgi++) { S += rs[wgi]; Q2 += rq[wgi]; }
        double n = (double)Bn*Ln;
        double m = S/n;
        double var = Q2/n - m*m;
        float rstd = (float)rsqrt(var + (double)EPSf);
        g_scale2[h] = g2[h]*rstd;
        g_shift2[h] = b2[h] - (float)m*rstd*g2[h];
    }
}

// ---------------- posterior gate ----------------
__global__ void gate_kernel(const float* __restrict__ Wp, const float* __restrict__ bp) {
    int idx = blockIdx.x*blockDim.x + threadIdx.x;
    if (idx >= Bn*Ln) return;
    int b = idx >> 10, l = idx & (Ln-1);
    float z0 = bp[0], z1 = bp[1];
    #pragma unroll
    for (int h = 0; h < Hn; h++) {
        float wn = g_w[(b*Hn + h)*Ln + l]*g_scale2[h] + g_shift2[h];
        z0 += Wp[h]      * wn;
        z1 += Wp[Hn + h] * wn;
    }
    float d = z1 - z0;
    g_p[idx] = 1.f/(1.f + __expf(d));
}

// ---------------- final masked softmax ----------------
__global__ void final_kernel(float* __restrict__ out) {
    int b = blockIdx.x, l = threadIdx.x;
    __shared__ float redm[32], redsum[32], bc[2];
    const float NEG_INF = __int_as_float(0xff800000);
    float x = g_valid[b*Ln + l] ? g_p[b*Ln + l] : NEG_INF;
    int warp = l >> 5, lane = l & 31;
    float m = x;
    #pragma unroll
    for (int o = 16; o; o >>= 1) m = fmaxf(m, __shfl_xor_sync(0xffffffffu, m, o));
    if (lane == 0) redm[warp] = m;
    __syncthreads();
    if (warp == 0) {
        m = redm[lane];
        #pragma unroll
        for (int o = 16; o; o >>= 1) m = fmaxf(m, __shfl_xor_sync(0xffffffffu, m, o));
        if (lane == 0) bc[0] = m;
    }
    __syncthreads();
    m = bc[0];
    float e = __expf(x - m);
    float s = e;
    #pragma unroll
    for (int o = 16; o; o >>= 1) s += __shfl_xor_sync(0xffffffffu, s, o);
    if (lane == 0) redsum[warp] = s;
    __syncthreads();
    if (warp == 0) {
        s = redsum[lane];
        #pragma unroll
        for (int o = 16; o; o >>= 1) s += __shfl_xor_sync(0xffffffffu, s, o);
        if (lane == 0) bc[1] = s;
    }
    __syncthreads();
    out[OFF_W + b*Ln + l] = e / bc[1];
}

// ---------------- launch ----------------
extern "C" void kernel_launch(void* const* d_in, const int* in_sizes, int n_in,
                              void* d_out, int out_size) {
    const float* Q  = (const float*)d_in[0];
    const float* K  = (const float*)d_in[1];
    const float* V  = (const float*)d_in[2];
    const unsigned int* bx = (const unsigned int*)d_in[4];
    const float* g1 = (const float*)d_in[5];
    const float* b1 = (const float*)d_in[6];
    const float* g2 = (const float*)d_in[7];
    const float* b2 = (const float*)d_in[8];
    const float* Wp = (const float*)d_in[9];
    const float* bp = (const float*)d_in[10];
    float* out = (float*)d_out;

    // smem: max(half tiles (256+128)*136*2 = 104448, float staging 256*132*4 = 135168)
    const int SMG = 256*CLD*4;   // 135168
    cudaFuncSetAttribute(gemm_kernel, cudaFuncAttributeMaxDynamicSharedMemorySize, SMG);

    zero_kernel<<<(BHn*Ln + 255)/256, 256>>>();
    mask_kernel<<<1, 256>>>(bx);
    vout_kernel<<<(BHn*Ln*DHn/4 + 255)/256, 256>>>(V, out);
    sq_kernel<<<(2*BHn*Ln*32 + 255)/256, 256>>>(Q, K);
    gemm_kernel<<<dim3(Ln/128, Ln/256, BHn), 256, SMG>>>(Q, K, out);
    stats1_kernel<<<1, 32>>>(g1, b1);
    softmax_kernel<<<BHn*(Ln/16), 512>>>(out);
    stats2_kernel<<<Hn, 256>>>(g2, b2);
    gate_kernel<<<(Bn*Ln + 255)/256, 256>>>(Wp, bp);
    final_kernel<<<Bn, Ln>>>(out);
}

// round 8
// speedup vs baseline: 2.6962x; 1.1050x over previous
#include <cuda_runtime.h>
#include <mma.h>
#include <cuda_fp16.h>
#include <cstdint>

using namespace nvcuda;

#define Bn  4
#define Ln  1024
#define Dn  768
#define Hn  6
#define DHn 128
#define BHn (Bn*Hn)
#define EPSf 1e-5f
#define GLDH 136   /* half leading dim: 128 + 8 (16B pad, conflict-free ldmatrix) */
#define CLD  132   /* epilogue float staging leading dim */

#define OFF_CO 0
#define OFF_W  (BHn*Ln*Ln)          /* 25165824 */
#define OFF_V  (OFF_W + Bn*Ln)      /* 25169920 */

// ---------------- scratch ----------------
__device__ float  g_q2[BHn*Ln];
__device__ float  g_k2[BHn*Ln];
__device__ double g_sum1[Hn];
__device__ double g_sumsq1[Hn];
__device__ float  g_scale1[Hn];
__device__ float  g_shift1[Hn];
__device__ float  g_w[BHn*Ln];
__device__ float  g_scale2[Hn];
__device__ float  g_shift2[Hn];
__device__ float  g_p[Bn*Ln];
__device__ unsigned char g_valid[Bn*Ln];

// ---------------- zero accumulators ----------------
__global__ void zero_kernel() {
    int idx = blockIdx.x*blockDim.x + threadIdx.x;
    if (idx < BHn*Ln) g_w[idx] = 0.f;
    if (idx < Hn) { g_sum1[idx] = 0.0; g_sumsq1[idx] = 0.0; }
}

// ---------------- mask: derive valid[] from bx_packed with dtype sniff ----------------
__global__ void mask_kernel(const unsigned int* w) {
    __shared__ int s_float, s_byte;
    if (threadIdx.x == 0) { s_float = 0; s_byte = 0; }
    __syncthreads();
    for (int i = threadIdx.x; i < (Bn*Ln)/4; i += blockDim.x) {
        unsigned v = w[i];
        if (v == 0x3f800000u) atomicOr(&s_float, 1);
        else if (v > 1u)      atomicOr(&s_byte, 1);
    }
    __syncthreads();
    int byte_mode = (!s_float) && s_byte;
    const unsigned char* bytes = (const unsigned char*)w;
    for (int i = threadIdx.x; i < Bn*Ln; i += blockDim.x) {
        bool padded = byte_mode ? (bytes[i] != 0) : (w[i] != 0u);
        g_valid[i] = padded ? 0 : 1;
    }
}

// ---------------- Vh output: transpose copy ----------------
__global__ void vout_kernel(const float* __restrict__ V, float* __restrict__ out) {
    int idx = blockIdx.x*blockDim.x + threadIdx.x;
    if (idx >= BHn*Ln*DHn/4) return;
    int d4 = idx & 31;
    int l  = (idx >> 5) & (Ln-1);
    int h  = (idx >> 15) % Hn;
    int b  = idx / (32*Ln*Hn);
    float4 v = *(const float4*)(V + ((size_t)(b*Ln + l))*Dn + h*DHn + d4*4);
    ((float4*)(out + OFF_V))[idx] = v;
}

// ---------------- squared norms: full-row contiguous reads, all 6 heads per warp ----------------
__global__ void sq_kernel(const float* __restrict__ Q, const float* __restrict__ K) {
    int gw = (blockIdx.x*blockDim.x + threadIdx.x) >> 5;
    int lane = threadIdx.x & 31;
    if (gw >= 2*Bn*Ln) return;
    int t = gw / (Bn*Ln);
    int r = gw % (Bn*Ln);               // b*Ln + l
    const float* src = (t ? K : Q) + (size_t)r*Dn;
    float* dst = t ? g_k2 : g_q2;
    int b = r >> 10, l = r & (Ln-1);
    float4 x[Hn];
    #pragma unroll
    for (int hh = 0; hh < Hn; hh++) x[hh] = ((const float4*)src)[hh*32 + lane];
    #pragma unroll
    for (int hh = 0; hh < Hn; hh++) {
        float s = x[hh].x*x[hh].x + x[hh].y*x[hh].y + x[hh].z*x[hh].z + x[hh].w*x[hh].w;
        #pragma unroll
        for (int o = 16; o; o >>= 1) s += __shfl_xor_sync(0xffffffffu, s, o);
        if (lane == 0) dst[(b*Hn + hh)*Ln + l] = s;
    }
}

// ---------------- main GEMM (fp16 wmma): S = 2QK^T - q2 - k2 -> co, + BN1 stats ----------------
// CTA tile 128x128, 128 threads, warp tile 64x64 (2x2 warp grid), K=128 resident, 2 CTAs/SM.
__global__ void __launch_bounds__(128, 2) gemm_kernel(const float* __restrict__ Q,
                                                      const float* __restrict__ K,
                                                      float* __restrict__ co) {
    extern __shared__ char smraw[];
    __half* As = (__half*)smraw;                    // 128 x GLDH
    __half* Bs = As + 128*GLDH;                     // 128 x GLDH
    float*  Cs = (float*)smraw;                     // alias after mma (128 x CLD)
    __shared__ float q2s[128], k2s[128];
    __shared__ double rs[4], rq[4];

    int bh = blockIdx.z; int b = bh / Hn, h = bh % Hn;
    int bi0 = blockIdx.y*128, bj0 = blockIdx.x*128;
    const float* Qb = Q + (size_t)b*Ln*Dn + h*DHn;
    const float* Kb = K + (size_t)b*Ln*Dn + h*DHn;
    int tid = threadIdx.x, warp = tid >> 5, lane = tid & 31;

    q2s[tid] = g_q2[bh*Ln + bi0 + tid];
    k2s[tid] = g_k2[bh*Ln + bj0 + tid];

    // load A (128x128) + B (128x128) as half
    #pragma unroll
    for (int i = 0; i < 32; i++) {
        int t = tid + i*128;            // 4096 float4 for A
        int r = t >> 5, c = t & 31;
        float4 q = *(const float4*)(Qb + (size_t)(bi0 + r)*Dn + c*4);
        *(half2*)&As[r*GLDH + c*4 + 0] = __floats2half2_rn(q.x, q.y);
        *(half2*)&As[r*GLDH + c*4 + 2] = __floats2half2_rn(q.z, q.w);
    }
    #pragma unroll
    for (int i = 0; i < 32; i++) {
        int t = tid + i*128;
        int r = t >> 5, c = t & 31;
        float4 k = *(const float4*)(Kb + (size_t)(bj0 + r)*Dn + c*4);
        *(half2*)&Bs[r*GLDH + c*4 + 0] = __floats2half2_rn(k.x, k.y);
        *(half2*)&Bs[r*GLDH + c*4 + 2] = __floats2half2_rn(k.z, k.w);
    }
    __syncthreads();

    // warp grid: 2 (M) x 2 (N); warp tile 64x64; k-step 16
    int wm = warp & 1, wn = warp >> 1;
    wmma::fragment<wmma::accumulator, 16,16,16, float> acc[4][4];
    #pragma unroll
    for (int m = 0; m < 4; m++)
        #pragma unroll
        for (int n = 0; n < 4; n++) wmma::fill_fragment(acc[m][n], 0.f);
    #pragma unroll
    for (int k = 0; k < 128; k += 16) {
        wmma::fragment<wmma::matrix_a, 16,16,16, __half, wmma::row_major> af[4];
        wmma::fragment<wmma::matrix_b, 16,16,16, __half, wmma::col_major> bf[4];
        #pragma unroll
        for (int m = 0; m < 4; m++)
            wmma::load_matrix_sync(af[m], As + (wm*64 + m*16)*GLDH + k, GLDH);
        #pragma unroll
        for (int n = 0; n < 4; n++)
            wmma::load_matrix_sync(bf[n], Bs + (wn*64 + n*16)*GLDH + k, GLDH);
        #pragma unroll
        for (int m = 0; m < 4; m++)
            #pragma unroll
            for (int n = 0; n < 4; n++)
                wmma::mma_sync(acc[m][n], af[m], bf[n], acc[m][n]);
    }
    __syncthreads();
    #pragma unroll
    for (int m = 0; m < 4; m++)
        #pragma unroll
        for (int n = 0; n < 4; n++)
            wmma::store_matrix_sync(Cs + (wm*64 + m*16)*CLD + wn*64 + n*16, acc[m][n], CLD,
                                    wmma::mem_row_major);
    __syncthreads();

    // epilogue: s = 2c - q2 - k2, raw write to co, stats
    float lsum = 0.f, lsq = 0.f;
    #pragma unroll
    for (int i = 0; i < 32; i++) {
        int f = tid + i*128;            // 4096 float4
        int r = f >> 5, c4 = f & 31;
        float4 c = *(const float4*)&Cs[r*CLD + c4*4];
        float q2v = q2s[r];
        float4 s4;
        s4.x = 2.f*c.x - q2v - k2s[c4*4+0];
        s4.y = 2.f*c.y - q2v - k2s[c4*4+1];
        s4.z = 2.f*c.z - q2v - k2s[c4*4+2];
        s4.w = 2.f*c.w - q2v - k2s[c4*4+3];
        *(float4*)(co + ((size_t)(bh*Ln + bi0 + r))*Ln + bj0 + c4*4) = s4;
        lsum += s4.x + s4.y + s4.z + s4.w;
        lsq  += s4.x*s4.x + s4.y*s4.y + s4.z*s4.z + s4.w*s4.w;
    }
    double ds = (double)lsum, dq = (double)lsq;
    #pragma unroll
    for (int o = 16; o; o >>= 1) {
        ds += __shfl_xor_sync(0xffffffffu, ds, o);
        dq += __shfl_xor_sync(0xffffffffu, dq, o);
    }
    if (lane == 0) { rs[warp] = ds; rq[warp] = dq; }
    __syncthreads();
    if (tid == 0) {
        double S = rs[0]+rs[1]+rs[2]+rs[3];
        double Q2 = rq[0]+rq[1]+rq[2]+rq[3];
        atomicAdd(&g_sum1[h], S); atomicAdd(&g_sumsq1[h], Q2);
    }
}

// ---------------- BN1 stats finalize ----------------
__global__ void stats1_kernel(const float* __restrict__ g1, const float* __restrict__ b1) {
    int h = threadIdx.x;
    if (h < Hn) {
        double n = (double)Bn*Ln*Ln;
        double m = g_sum1[h]/n;
        double var = g_sumsq1[h]/n - m*m;
        float rstd = (float)rsqrt(var + (double)EPSf);
        g_scale1[h] = g1[h]*rstd;
        g_shift1[h] = b1[h] - (float)m*rstd*g1[h];
    }
}

// ---------------- normalize + mask(0) + softmax (in place) + column sums ----------------
__global__ void __launch_bounds__(512) softmax_kernel(float* __restrict__ co) {
    __shared__ float colsum[Ln];
    __shared__ unsigned char sval[Ln];
    int bh = blockIdx.x >> 6;
    int rb = blockIdx.x & 63;
    int b = bh / Hn, h = bh % Hn;
    int tid = threadIdx.x, warp = tid >> 5, lane = tid & 31;
    for (int j = tid; j < Ln; j += 512) { colsum[j] = 0.f; sval[j] = g_valid[b*Ln + j]; }
    __syncthreads();

    int i = rb*16 + warp;
    bool rowvalid = sval[i] != 0;
    float scale = g_scale1[h], shift = g_shift1[h];
    float4* Sr = (float4*)(co + ((size_t)bh*Ln + i)*Ln);

    float v[32];
    float mx = -1e30f;
    #pragma unroll
    for (int c = 0; c < 8; c++) {
        float4 x = Sr[c*32 + lane];
        int j0 = c*128 + lane*4;
        float a0 = (rowvalid && sval[j0+0]) ? x.x*scale + shift : 0.f;
        float a1 = (rowvalid && sval[j0+1]) ? x.y*scale + shift : 0.f;
        float a2 = (rowvalid && sval[j0+2]) ? x.z*scale + shift : 0.f;
        float a3 = (rowvalid && sval[j0+3]) ? x.w*scale + shift : 0.f;
        v[c*4+0]=a0; v[c*4+1]=a1; v[c*4+2]=a2; v[c*4+3]=a3;
        mx = fmaxf(mx, fmaxf(fmaxf(a0,a1), fmaxf(a2,a3)));
    }
    #pragma unroll
    for (int o = 16; o; o >>= 1) mx = fmaxf(mx, __shfl_xor_sync(0xffffffffu, mx, o));
    float sum = 0.f;
    #pragma unroll
    for (int t = 0; t < 32; t++) { float e = __expf(v[t] - mx); v[t] = e; sum += e; }
    #pragma unroll
    for (int o = 16; o; o >>= 1) sum += __shfl_xor_sync(0xffffffffu, sum, o);
    float inv = 1.0f / sum;

    #pragma unroll
    for (int c = 0; c < 8; c++) {
        int j0 = c*128 + lane*4;
        float4 o4;
        o4.x = v[c*4+0]*inv; o4.y = v[c*4+1]*inv; o4.z = v[c*4+2]*inv; o4.w = v[c*4+3]*inv;
        Sr[c*32 + lane] = o4;
        atomicAdd(&colsum[j0+0], o4.x);
        atomicAdd(&colsum[j0+1], o4.y);
        atomicAdd(&colsum[j0+2], o4.z);
        atomicAdd(&colsum[j0+3], o4.w);
    }
    __syncthreads();
    for (int j = tid; j < Ln; j += 512) atomicAdd(&g_w[bh*Ln + j], colsum[j]);
}

// ---------------- BN2 stats ----------------
__global__ void stats2_kernel(const float* __restrict__ g2, const float* __restrict__ b2) {
    int h = blockIdx.x;
    int tid = threadIdx.x;
    float ls = 0.f, lq = 0.f;
    for (int b = 0; b < Bn; b++) {
        const float* wp = g_w + (b*Hn + h)*Ln;
        for (int j = tid; j < Ln; j += 256) { float x = wp[j]; ls += x; lq += x*x; }
    }
    double ds = (double)ls, dq = (double)lq;
    #pragma unroll
    for (int o = 16; o; o >>= 1) {
        ds += __shfl_xor_sync(0xffffffffu, ds, o);
        dq += __shfl_xor_sync(0xffffffffu, dq, o);
    }
    __shared__ double rs[8], rq[8];
    int warp = tid >> 5, lane = tid & 31;
    if (lane == 0) { rs[warp] = ds; rq[warp] = dq; }
    __syncthreads();
    if (tid == 0) {
        double S = 0.0, Q2 = 0.0;
        for (int wgi = 0; wgi < 8; wgi++) { S += rs[wgi]; Q2 += rq[wgi]; }
        double n = (double)Bn*Ln;
        double m = S/n;
        double var = Q2/n - m*m;
        float rstd = (float)rsqrt(var + (double)EPSf);
        g_scale2[h] = g2[h]*rstd;
        g_shift2[h] = b2[h] - (float)m*rstd*g2[h];
    }
}

// ---------------- posterior gate ----------------
__global__ void gate_kernel(const float* __restrict__ Wp, const float* __restrict__ bp) {
    int idx = blockIdx.x*blockDim.x + threadIdx.x;
    if (idx >= Bn*Ln) return;
    int b = idx >> 10, l = idx & (Ln-1);
    float z0 = bp[0], z1 = bp[1];
    #pragma unroll
    for (int h = 0; h < Hn; h++) {
        float wn = g_w[(b*Hn + h)*Ln + l]*g_scale2[h] + g_shift2[h];
        z0 += Wp[h]      * wn;
        z1 += Wp[Hn + h] * wn;
    }
    float d = z1 - z0;
    g_p[idx] = 1.f/(1.f + __expf(d));
}

// ---------------- final masked softmax ----------------
__global__ void final_kernel(float* __restrict__ out) {
    int b = blockIdx.x, l = threadIdx.x;
    __shared__ float redm[32], redsum[32], bc[2];
    const float NEG_INF = __int_as_float(0xff800000);
    float x = g_valid[b*Ln + l] ? g_p[b*Ln + l] : NEG_INF;
    int warp = l >> 5, lane = l & 31;
    float m = x;
    #pragma unroll
    for (int o = 16; o; o >>= 1) m = fmaxf(m, __shfl_xor_sync(0xffffffffu, m, o));
    if (lane == 0) redm[warp] = m;
    __syncthreads();
    if (warp == 0) {
        m = redm[lane];
        #pragma unroll
        for (int o = 16; o; o >>= 1) m = fmaxf(m, __shfl_xor_sync(0xffffffffu, m, o));
        if (lane == 0) bc[0] = m;
    }
    __syncthreads();
    m = bc[0];
    float e = __expf(x - m);
    float s = e;
    #pragma unroll
    for (int o = 16; o; o >>= 1) s += __shfl_xor_sync(0xffffffffu, s, o);
    if (lane == 0) redsum[warp] = s;
    __syncthreads();
    if (warp == 0) {
        s = redsum[lane];
        #pragma unroll
        for (int o = 16; o; o >>= 1) s += __shfl_xor_sync(0xffffffffu, s, o);
        if (lane == 0) bc[1] = s;
    }
    __syncthreads();
    out[OFF_W + b*Ln + l] = e / bc[1];
}

// ---------------- launch ----------------
extern "C" void kernel_launch(void* const* d_in, const int* in_sizes, int n_in,
                              void* d_out, int out_size) {
    const float* Q  = (const float*)d_in[0];
    const float* K  = (const float*)d_in[1];
    const float* V  = (const float*)d_in[2];
    const unsigned int* bx = (const unsigned int*)d_in[4];
    const float* g1 = (const float*)d_in[5];
    const float* b1 = (const float*)d_in[6];
    const float* g2 = (const float*)d_in[7];
    const float* b2 = (const float*)d_in[8];
    const float* Wp = (const float*)d_in[9];
    const float* bp = (const float*)d_in[10];
    float* out = (float*)d_out;

    // smem: max(half tiles 2*128*136*2 = 69632, float staging 128*132*4 = 67584)
    const int SMG = 2*128*GLDH*2;   // 69632
    cudaFuncSetAttribute(gemm_kernel, cudaFuncAttributeMaxDynamicSharedMemorySize, SMG);

    zero_kernel<<<(BHn*Ln + 255)/256, 256>>>();
    mask_kernel<<<1, 256>>>(bx);
    vout_kernel<<<(BHn*Ln*DHn/4 + 255)/256, 256>>>(V, out);
    sq_kernel<<<(2*Bn*Ln*32 + 255)/256, 256>>>(Q, K);
    gemm_kernel<<<dim3(Ln/128, Ln/128, BHn), 128, SMG>>>(Q, K, out);
    stats1_kernel<<<1, 32>>>(g1, b1);
    softmax_kernel<<<BHn*(Ln/16), 512>>>(out);
    stats2_kernel<<<Hn, 256>>>(g2, b2);
    gate_kernel<<<(Bn*Ln + 255)/256, 256>>>(Wp, bp);
    final_kernel<<<Bn, Ln>>>(out);
}